// round 15
// baseline (speedup 1.0000x reference)
#include <cuda_runtime.h>
#include <cuda_fp16.h>
#include <math.h>

#define NN 80000
#define DD 64
#define EE 1280000
#define CAP 128   // padded adjacency capacity per node

// Scratch (__device__ globals; no allocation allowed in kernel_launch)
__device__ uint4 g_hH[NN * 8];     // h' = (X@W)*dinv packed fp16 (8 uint4/row)
__device__ uint2 g_H2[NN * 16];    // H = relu(...) packed fp16
__device__ float g_gg[NN];
__device__ int   g_cnt[NN];        // out-degree (gate denominator)
__device__ int   g_deg[NN];        // in-degree == build cursor
__device__ int   g_adj[NN * CAP];  // padded adjacency: srcs bucketed by dst

// ---------------------------------------------------------------------------
__global__ void k_init(int n) {
    int i = blockIdx.x * blockDim.x + threadIdx.x;
    if (i < n) {
        g_deg[i] = 0;
        g_cnt[i] = 0;
        g_gg[i]  = 0.f;
    }
}

// ---------------------------------------------------------------------------
// k_build: ONE indexing pass. Slot-claim atomic IS the degree counter.
// ---------------------------------------------------------------------------
__global__ void k_build(const int* __restrict__ src, const int* __restrict__ dst, int e) {
    int i = blockIdx.x * blockDim.x + threadIdx.x;
    if (i < e) {
        int s = src[i], d = dst[i];
        int pos = atomicAdd(&g_deg[d], 1);
        if (pos < CAP) g_adj[d * CAP + pos] = s;
        atomicAdd(&g_cnt[s], 1);
    }
}

// ---------------------------------------------------------------------------
// k_gemm: h' = (X @ W) * dinv_row, 4x8 register tile.
// Block = 128 threads covers 64 rows x 64 cols. Per k-step: 1 LDS.128 (x) +
// 2 LDS.128 (w) feed 32 FMA (10.7 FMA/LDS vs 8 for the old 4x4).
// dinv folded into the fp16 pack epilogue; each row's 8 cols = one ST.128.
// ---------------------------------------------------------------------------
#define XS_STRIDE 68
__global__ void __launch_bounds__(128) k_gemm(const float* __restrict__ X,
                                              const float* __restrict__ W, int n) {
    __shared__ float  Xsh[64 * XS_STRIDE];   // Xsh[k][row]
    __shared__ float4 Wsh[64 * 16];          // Wsh[k][cg]

    int tid  = threadIdx.x;
    int base = blockIdx.x * 64;

    // Stage W: 1024 float4, 8 per thread.
    const float4* W4 = (const float4*)W;
#pragma unroll
    for (int i = 0; i < 8; i++) Wsh[tid + 128 * i] = W4[tid + 128 * i];

    // Stage X transposed: 1024 float4, 8 per thread.
#pragma unroll
    for (int i = 0; i < 8; i++) {
        int idx = tid + 128 * i;         // 0..1023
        int row = idx & 63;
        int kk  = idx >> 6;              // float4 index along k: 0..15
        int gr  = base + row;
        float4 v = (gr < n) ? ((const float4*)(X + (size_t)gr * 64))[kk]
                            : make_float4(0.f, 0.f, 0.f, 0.f);
        int k0 = kk * 4;
        Xsh[(k0 + 0) * XS_STRIDE + row] = v.x;
        Xsh[(k0 + 1) * XS_STRIDE + row] = v.y;
        Xsh[(k0 + 2) * XS_STRIDE + row] = v.z;
        Xsh[(k0 + 3) * XS_STRIDE + row] = v.w;
    }
    __syncthreads();

    int cg = tid & 7;         // col group (8 cols: cg*8 .. cg*8+7)
    int rg = tid >> 3;        // row group (4 rows: rg*4 .. rg*4+3)

    float acc[4][8];
#pragma unroll
    for (int j = 0; j < 4; j++)
#pragma unroll
        for (int c = 0; c < 8; c++) acc[j][c] = 0.f;

#pragma unroll 8
    for (int k = 0; k < 64; k++) {
        float4 xv = *(const float4*)&Xsh[k * XS_STRIDE + rg * 4];
        float4 w0 = Wsh[k * 16 + cg * 2];
        float4 w1 = Wsh[k * 16 + cg * 2 + 1];
        float x[4] = {xv.x, xv.y, xv.z, xv.w};
#pragma unroll
        for (int j = 0; j < 4; j++) {
            acc[j][0] = fmaf(x[j], w0.x, acc[j][0]);
            acc[j][1] = fmaf(x[j], w0.y, acc[j][1]);
            acc[j][2] = fmaf(x[j], w0.z, acc[j][2]);
            acc[j][3] = fmaf(x[j], w0.w, acc[j][3]);
            acc[j][4] = fmaf(x[j], w1.x, acc[j][4]);
            acc[j][5] = fmaf(x[j], w1.y, acc[j][5]);
            acc[j][6] = fmaf(x[j], w1.z, acc[j][6]);
            acc[j][7] = fmaf(x[j], w1.w, acc[j][7]);
        }
    }

#pragma unroll
    for (int j = 0; j < 4; j++) {
        int row = base + rg * 4 + j;
        if (row < n) {
            float di = rsqrtf((float)(g_deg[row] + 1));   // fold dinv into h'
            __half2 h0 = __floats2half2_rn(acc[j][0] * di, acc[j][1] * di);
            __half2 h1 = __floats2half2_rn(acc[j][2] * di, acc[j][3] * di);
            __half2 h2 = __floats2half2_rn(acc[j][4] * di, acc[j][5] * di);
            __half2 h3 = __floats2half2_rn(acc[j][6] * di, acc[j][7] * di);
            uint4 p;
            p.x = *(unsigned int*)&h0;
            p.y = *(unsigned int*)&h1;
            p.z = *(unsigned int*)&h2;
            p.w = *(unsigned int*)&h3;
            g_hH[row * 8 + cg] = p;
        }
    }
}

// ---------------------------------------------------------------------------
// k_agg: warp per node (R12 measured-good form: lane owns cols 2l,2l+1, one
// 4B load per lane -> coalesced 128B per neighbor). Neighbor ids fetched as
// int4 (1 LDG.128 per 4 ids). agg = dinv_d * (sum h'[s] + h'[d]).
// ---------------------------------------------------------------------------
__global__ void __launch_bounds__(256) k_agg(const float* __restrict__ b, int n) {
    int warp = (blockIdx.x * blockDim.x + threadIdx.x) >> 5;
    int lane = threadIdx.x & 31;
    if (warp >= n) return;
    int d = warp;

    const unsigned int* h2 = (const unsigned int*)g_hH;  // 32 uints per row
    int cnt = g_deg[d];
    float dinv_d = rsqrtf((float)(cnt + 1));   // +1 self loop
    const int* row = &g_adj[d * CAP];

    float2 acc = make_float2(0.f, 0.f);

    int j = 0;
    for (; j + 4 <= cnt; j += 4) {
        int4 i4 = *(const int4*)&row[j];     // 1 LDG.128 for 4 ids
        float2 ha = __half22float2(*(const __half2*)&h2[i4.x * 32 + lane]);
        float2 hb = __half22float2(*(const __half2*)&h2[i4.y * 32 + lane]);
        float2 hc = __half22float2(*(const __half2*)&h2[i4.z * 32 + lane]);
        float2 hd = __half22float2(*(const __half2*)&h2[i4.w * 32 + lane]);
        acc.x += ha.x + hb.x + hc.x + hd.x;
        acc.y += ha.y + hb.y + hc.y + hd.y;
    }
    for (; j < cnt; j++) {
        int s = row[j];
        float2 hv = __half22float2(*(const __half2*)&h2[s * 32 + lane]);
        acc.x += hv.x;
        acc.y += hv.y;
    }

    // self loop contributes h'[d]
    float2 hd0 = __half22float2(*(const __half2*)&h2[d * 32 + lane]);
    acc.x += hd0.x;
    acc.y += hd0.y;

    float2 bb = ((const float2*)b)[lane];
    float rx = fmaxf(fmaf(acc.x, dinv_d, bb.x), 0.f);
    float ry = fmaxf(fmaf(acc.y, dinv_d, bb.y), 0.f);
    __half2 hh = __floats2half2_rn(rx, ry);
    ((unsigned int*)g_H2)[d * 32 + lane] = *(unsigned int*)&hh;
}

// ---------------------------------------------------------------------------
// k_gate: edge-parallel, HSUB2 diff before conversion (measured-good R13
// form). gg[src] += ||H_s - H_d||^2. 8 lanes/edge, uint4 per lane.
// ---------------------------------------------------------------------------
__global__ void k_gate(const int* __restrict__ src, const int* __restrict__ dst, int e) {
    int t = blockIdx.x * blockDim.x + threadIdx.x;
    int ei = t >> 3;
    int lane = t & 7;
    if (ei >= e) return;
    int r = src[ei];
    int c = dst[ei];
    const uint4* H = (const uint4*)g_H2;
    uint4 a = __ldg(&H[r * 8 + lane]);
    uint4 b = __ldg(&H[c * 8 + lane]);
    const unsigned int* au = (const unsigned int*)&a;
    const unsigned int* bu = (const unsigned int*)&b;
    float s = 0.f;
#pragma unroll
    for (int j = 0; j < 4; j++) {
        __half2 dh = __hsub2(*(const __half2*)&au[j], *(const __half2*)&bu[j]);
        float2 df = __half22float2(dh);
        s = fmaf(df.x, df.x, s);
        s = fmaf(df.y, df.y, s);
    }
    s += __shfl_xor_sync(0xffffffffu, s, 4);
    s += __shfl_xor_sync(0xffffffffu, s, 2);
    s += __shfl_xor_sync(0xffffffffu, s, 1);
    if (lane == 0) atomicAdd(&g_gg[r], s);
}

__global__ void k_out(float* __restrict__ out, int n) {
    int i = blockIdx.x * blockDim.x + threadIdx.x;
    if (i < n) out[i] = tanhf(g_gg[i] / fmaxf((float)g_cnt[i], 1.f));
}

// ---------------------------------------------------------------------------
extern "C" void kernel_launch(void* const* d_in, const int* in_sizes, int n_in,
                              void* d_out, int out_size) {
    const float* X  = (const float*)d_in[0];
    const int*   ei = (const int*)d_in[1];
    const float* W  = (const float*)d_in[2];
    const float* b  = (const float*)d_in[3];
    float* out = (float*)d_out;

    int n = in_sizes[0] / DD;   // 80000
    int e = in_sizes[1] / 2;    // 1280000
    const int* src = ei;
    const int* dst = ei + e;

    const int T = 256;
    int g_n    = (n + T - 1) / T;
    int g_e    = (e + T - 1) / T;
    int g_rows = (n + 63) / 64;
    int g_warp = (n * 32 + T - 1) / T;
    long long e8 = (long long)e * 8;
    int g_e8 = (int)((e8 + T - 1) / T);

    k_init <<<g_n, T>>>(n);
    k_build<<<g_e, T>>>(src, dst, e);
    k_gemm <<<g_rows, 128>>>(X, W, n);
    k_agg  <<<g_warp, T>>>(b, n);
    k_gate <<<g_e8, T>>>(src, dst, e);
    k_out  <<<g_n, T>>>(out, n);
}

// round 16
// speedup vs baseline: 1.0737x; 1.0737x over previous
#include <cuda_runtime.h>
#include <cuda_fp16.h>
#include <math.h>

#define NN 80000
#define DD 64
#define EE 1280000
#define CAP 128   // padded adjacency capacity per node

// Scratch (__device__ globals; no allocation allowed in kernel_launch)
__device__ uint2 g_hH[NN * 16];    // h' = (X@W)*dinv packed fp16 (32 uints/row)
__device__ uint2 g_H2[NN * 16];    // H = relu(...) packed fp16
__device__ float g_gg[NN];
__device__ int   g_cnt[NN];        // out-degree (gate denominator)
__device__ int   g_deg[NN];        // in-degree == build cursor
__device__ int   g_adj[NN * CAP];  // padded adjacency: srcs bucketed by dst

// ---------------------------------------------------------------------------
__global__ void k_init(int n) {
    int i = blockIdx.x * blockDim.x + threadIdx.x;
    if (i < n) {
        g_deg[i] = 0;
        g_cnt[i] = 0;
        g_gg[i]  = 0.f;
    }
}

// ---------------------------------------------------------------------------
// k_build: ONE indexing pass. Slot-claim atomic IS the degree counter.
// ---------------------------------------------------------------------------
__global__ void k_build(const int* __restrict__ src, const int* __restrict__ dst, int e) {
    int i = blockIdx.x * blockDim.x + threadIdx.x;
    if (i < e) {
        int s = src[i], d = dst[i];
        int pos = atomicAdd(&g_deg[d], 1);
        if (pos < CAP) g_adj[d * CAP + pos] = s;
        atomicAdd(&g_cnt[s], 1);
    }
}

// ---------------------------------------------------------------------------
// k_gemm: h' = (X @ W) * dinv_row, 4x4 register tile @ 256 threads
// (measured-optimal shape: 27.1us across three rounds). dinv folded into the
// fp16 pack epilogue (runs after k_build, so g_deg is final).
// ---------------------------------------------------------------------------
#define XS_STRIDE 68
__global__ void __launch_bounds__(256) k_gemm(const float* __restrict__ X,
                                              const float* __restrict__ W, int n) {
    __shared__ float  Xsh[64 * XS_STRIDE];   // Xsh[k][row]
    __shared__ float4 Wsh[64 * 16];          // Wsh[k][cg]

    int tid  = threadIdx.x;
    int base = blockIdx.x * 64;

    const float4* W4 = (const float4*)W;
#pragma unroll
    for (int i = 0; i < 4; i++) Wsh[tid + 256 * i] = W4[tid + 256 * i];

#pragma unroll
    for (int i = 0; i < 4; i++) {
        int idx = tid + 256 * i;
        int row = idx & 63;
        int kk  = idx >> 6;
        int gr  = base + row;
        float4 v = (gr < n) ? ((const float4*)(X + (size_t)gr * 64))[kk]
                            : make_float4(0.f, 0.f, 0.f, 0.f);
        int k0 = kk * 4;
        Xsh[(k0 + 0) * XS_STRIDE + row] = v.x;
        Xsh[(k0 + 1) * XS_STRIDE + row] = v.y;
        Xsh[(k0 + 2) * XS_STRIDE + row] = v.z;
        Xsh[(k0 + 3) * XS_STRIDE + row] = v.w;
    }
    __syncthreads();

    int cg = tid & 15;
    int rg = tid >> 4;

    float4 acc0 = make_float4(0.f, 0.f, 0.f, 0.f);
    float4 acc1 = make_float4(0.f, 0.f, 0.f, 0.f);
    float4 acc2 = make_float4(0.f, 0.f, 0.f, 0.f);
    float4 acc3 = make_float4(0.f, 0.f, 0.f, 0.f);

#pragma unroll
    for (int k = 0; k < 64; k++) {
        float4 w  = Wsh[k * 16 + cg];
        float4 xv = *(const float4*)&Xsh[k * XS_STRIDE + rg * 4];
        acc0.x += xv.x * w.x; acc0.y += xv.x * w.y; acc0.z += xv.x * w.z; acc0.w += xv.x * w.w;
        acc1.x += xv.y * w.x; acc1.y += xv.y * w.y; acc1.z += xv.y * w.z; acc1.w += xv.y * w.w;
        acc2.x += xv.z * w.x; acc2.y += xv.z * w.y; acc2.z += xv.z * w.z; acc2.w += xv.z * w.w;
        acc3.x += xv.w * w.x; acc3.y += xv.w * w.y; acc3.z += xv.w * w.z; acc3.w += xv.w * w.w;
    }

    int r0 = base + rg * 4;
#pragma unroll
    for (int j = 0; j < 4; j++) {
        float4 a = (j == 0) ? acc0 : (j == 1) ? acc1 : (j == 2) ? acc2 : acc3;
        int row = r0 + j;
        if (row < n) {
            float di = rsqrtf((float)(g_deg[row] + 1));   // fold dinv into h'
            __half2 lo = __floats2half2_rn(a.x * di, a.y * di);
            __half2 hi = __floats2half2_rn(a.z * di, a.w * di);
            uint2 p;
            p.x = *(unsigned int*)&lo;
            p.y = *(unsigned int*)&hi;
            g_hH[row * 16 + cg] = p;
        }
    }
}

// ---------------------------------------------------------------------------
// k_agg: warp per node (lane owns cols 2l,2l+1; coalesced 128B per neighbor).
// Neighbor ids via int4 (1 LDG.128 per 4). Per 4-group: depth-1 fp16 pair
// adds (2x HADD2) then 2 cvt + 4 FADD into fp32 acc (was 4 cvt + 8 FADD).
// agg = dinv_d * (sum h'[s] + h'[d]); fuses bias/relu/pack.
// ---------------------------------------------------------------------------
__global__ void __launch_bounds__(256) k_agg(const float* __restrict__ b, int n) {
    int warp = (blockIdx.x * blockDim.x + threadIdx.x) >> 5;
    int lane = threadIdx.x & 31;
    if (warp >= n) return;
    int d = warp;

    const unsigned int* h2 = (const unsigned int*)g_hH;  // 32 uints per row
    int cnt = g_deg[d];
    float dinv_d = rsqrtf((float)(cnt + 1));   // +1 self loop
    const int* row = &g_adj[d * CAP];

    float2 acc = make_float2(0.f, 0.f);

    int j = 0;
    for (; j + 4 <= cnt; j += 4) {
        int4 i4 = *(const int4*)&row[j];     // 1 LDG.128 for 4 ids
        __half2 va = *(const __half2*)&h2[i4.x * 32 + lane];
        __half2 vb = *(const __half2*)&h2[i4.y * 32 + lane];
        __half2 vc = *(const __half2*)&h2[i4.z * 32 + lane];
        __half2 vd = *(const __half2*)&h2[i4.w * 32 + lane];
        float2 p0 = __half22float2(__hadd2(va, vb));  // depth-1 fp16 pair add
        float2 p1 = __half22float2(__hadd2(vc, vd));
        acc.x += p0.x + p1.x;
        acc.y += p0.y + p1.y;
    }
    for (; j < cnt; j++) {
        int s = row[j];
        float2 hv = __half22float2(*(const __half2*)&h2[s * 32 + lane]);
        acc.x += hv.x;
        acc.y += hv.y;
    }

    // self loop contributes h'[d]
    float2 hd0 = __half22float2(*(const __half2*)&h2[d * 32 + lane]);
    acc.x += hd0.x;
    acc.y += hd0.y;

    float2 bb = ((const float2*)b)[lane];
    float rx = fmaxf(fmaf(acc.x, dinv_d, bb.x), 0.f);
    float ry = fmaxf(fmaf(acc.y, dinv_d, bb.y), 0.f);
    __half2 hh = __floats2half2_rn(rx, ry);
    ((unsigned int*)g_H2)[d * 32 + lane] = *(unsigned int*)&hh;
}

// ---------------------------------------------------------------------------
// k_gate: edge-parallel, HSUB2 diff before conversion (measured-good form).
// gg[src] += ||H_s - H_d||^2. 8 lanes/edge, uint4 per lane.
// ---------------------------------------------------------------------------
__global__ void k_gate(const int* __restrict__ src, const int* __restrict__ dst, int e) {
    int t = blockIdx.x * blockDim.x + threadIdx.x;
    int ei = t >> 3;
    int lane = t & 7;
    if (ei >= e) return;
    int r = src[ei];
    int c = dst[ei];
    const uint4* H = (const uint4*)g_H2;
    uint4 a = __ldg(&H[r * 8 + lane]);
    uint4 b = __ldg(&H[c * 8 + lane]);
    const unsigned int* au = (const unsigned int*)&a;
    const unsigned int* bu = (const unsigned int*)&b;
    float s = 0.f;
#pragma unroll
    for (int j = 0; j < 4; j++) {
        __half2 dh = __hsub2(*(const __half2*)&au[j], *(const __half2*)&bu[j]);
        float2 df = __half22float2(dh);
        s = fmaf(df.x, df.x, s);
        s = fmaf(df.y, df.y, s);
    }
    s += __shfl_xor_sync(0xffffffffu, s, 4);
    s += __shfl_xor_sync(0xffffffffu, s, 2);
    s += __shfl_xor_sync(0xffffffffu, s, 1);
    if (lane == 0) atomicAdd(&g_gg[r], s);
}

__global__ void k_out(float* __restrict__ out, int n) {
    int i = blockIdx.x * blockDim.x + threadIdx.x;
    if (i < n) out[i] = tanhf(g_gg[i] / fmaxf((float)g_cnt[i], 1.f));
}

// ---------------------------------------------------------------------------
extern "C" void kernel_launch(void* const* d_in, const int* in_sizes, int n_in,
                              void* d_out, int out_size) {
    const float* X  = (const float*)d_in[0];
    const int*   ei = (const int*)d_in[1];
    const float* W  = (const float*)d_in[2];
    const float* b  = (const float*)d_in[3];
    float* out = (float*)d_out;

    int n = in_sizes[0] / DD;   // 80000
    int e = in_sizes[1] / 2;    // 1280000
    const int* src = ei;
    const int* dst = ei + e;

    const int T = 256;
    int g_n    = (n + T - 1) / T;
    int g_e    = (e + T - 1) / T;
    int g_rows = (n + 63) / 64;
    int g_warp = (n * 32 + T - 1) / T;
    long long e8 = (long long)e * 8;
    int g_e8 = (int)((e8 + T - 1) / T);

    k_init <<<g_n, T>>>(n);
    k_build<<<g_e, T>>>(src, dst, e);
    k_gemm <<<g_rows, T>>>(X, W, n);
    k_agg  <<<g_warp, T>>>(b, n);
    k_gate <<<g_e8, T>>>(src, dst, e);
    k_out  <<<g_n, T>>>(out, n);
}